// round 1
// baseline (speedup 1.0000x reference)
#include <cuda_runtime.h>

// Live computation (see analysis): out = MLP( (mean_p lidar[b,p,:]) @ wv )
// Everything else in the reference is dead because only the zero-padded last
// query row feeds the head, making attention a uniform average of V.

#define BATCH     16
#define N_POINTS  4096
#define LIDAR_C   256
#define D_MODEL   1024
#define H1        128
#define BIN_SIZE  256
#define SPLIT     64                      // point-dim split for reduction
#define PTS_PER_BLK (N_POINTS / SPLIT)    // 64

// scratch partial sums: [SPLIT][BATCH][LIDAR_C] = 4 MB
__device__ float g_partial[SPLIT * BATCH * LIDAR_C];

// ---------------------------------------------------------------------------
// Kernel 1: partial column sums of lidar over the point dimension.
// grid (BATCH, SPLIT), block 256 threads. Thread t owns channel t.
// Loads are fully coalesced (channel dim is contiguous, 1 KB per point row).
// ---------------------------------------------------------------------------
__global__ void __launch_bounds__(LIDAR_C)
lidar_reduce_kernel(const float* __restrict__ lidar)
{
    const int b = blockIdx.x;
    const int s = blockIdx.y;
    const int c = threadIdx.x;

    const float* base = lidar
        + ((size_t)b * N_POINTS + (size_t)s * PTS_PER_BLK) * LIDAR_C + c;

    float sum = 0.0f;
#pragma unroll 16
    for (int p = 0; p < PTS_PER_BLK; ++p)
        sum += __ldg(base + (size_t)p * LIDAR_C);

    g_partial[((size_t)s * BATCH + b) * LIDAR_C + c] = sum;
}

// ---------------------------------------------------------------------------
// Kernel 2: per-batch head. One block per batch, 1024 threads.
//   mean (256) -> bins = mean @ wv (1024) -> h1 = lrelu(bins@wo1+b1) (128)
//   -> h2 = lrelu(h1@wo2+b2) (128) -> out = h2@wo3+b3 (256)
// ---------------------------------------------------------------------------
__global__ void __launch_bounds__(1024)
head_kernel(const float* __restrict__ wv,    // [256,1024]
            const float* __restrict__ wo1,   // [1024,128]
            const float* __restrict__ b1,    // [128]
            const float* __restrict__ wo2,   // [128,128]
            const float* __restrict__ b2,    // [128]
            const float* __restrict__ wo3,   // [128,256]
            const float* __restrict__ b3,    // [256]
            float* __restrict__ out)         // [BATCH,256]
{
    const int b   = blockIdx.x;
    const int tid = threadIdx.x;

    __shared__ float s_mean[LIDAR_C];
    __shared__ float s_bins[D_MODEL];
    __shared__ float s_h1[H1];
    __shared__ float s_h2[H1];

    // fold the SPLIT partials -> mean
    if (tid < LIDAR_C) {
        float sum = 0.0f;
#pragma unroll 8
        for (int s = 0; s < SPLIT; ++s)
            sum += g_partial[((size_t)s * BATCH + b) * LIDAR_C + tid];
        s_mean[tid] = sum * (1.0f / (float)N_POINTS);
    }
    __syncthreads();

    // bins[j] = sum_c mean[c] * wv[c][j]   (each of 1024 threads owns one j)
    {
        float acc = 0.0f;
#pragma unroll 8
        for (int c = 0; c < LIDAR_C; ++c)
            acc += s_mean[c] * __ldg(&wv[(size_t)c * D_MODEL + tid]);
        s_bins[tid] = acc;
    }
    __syncthreads();

    // h1[j] = lrelu(sum_c bins[c] * wo1[c][j] + b1[j])
    if (tid < H1) {
        float acc = __ldg(&b1[tid]);
#pragma unroll 8
        for (int c = 0; c < D_MODEL; ++c)
            acc += s_bins[c] * __ldg(&wo1[(size_t)c * H1 + tid]);
        s_h1[tid] = (acc > 0.0f) ? acc : 0.01f * acc;
    }
    __syncthreads();

    // h2[j] = lrelu(sum_c h1[c] * wo2[c][j] + b2[j])
    if (tid < H1) {
        float acc = __ldg(&b2[tid]);
#pragma unroll 8
        for (int c = 0; c < H1; ++c)
            acc += s_h1[c] * __ldg(&wo2[(size_t)c * H1 + tid]);
        s_h2[tid] = (acc > 0.0f) ? acc : 0.01f * acc;
    }
    __syncthreads();

    // out[j] = sum_c h2[c] * wo3[c][j] + b3[j]
    if (tid < BIN_SIZE) {
        float acc = __ldg(&b3[tid]);
#pragma unroll 8
        for (int c = 0; c < H1; ++c)
            acc += s_h2[c] * __ldg(&wo3[(size_t)c * BIN_SIZE + tid]);
        out[(size_t)b * BIN_SIZE + tid] = acc;
    }
}

// ---------------------------------------------------------------------------
// Inputs (metadata order):
// 0 feature, 1 lidar, 2 conv1_w, 3 conv2_w, 4 wq, 5 wk, 6 wv,
// 7 wo1, 8 b1, 9 wo2, 10 b2, 11 wo3, 12 b3
// ---------------------------------------------------------------------------
extern "C" void kernel_launch(void* const* d_in, const int* in_sizes, int n_in,
                              void* d_out, int out_size)
{
    const float* lidar = (const float*)d_in[1];
    const float* wv    = (const float*)d_in[6];
    const float* wo1   = (const float*)d_in[7];
    const float* b1    = (const float*)d_in[8];
    const float* wo2   = (const float*)d_in[9];
    const float* b2    = (const float*)d_in[10];
    const float* wo3   = (const float*)d_in[11];
    const float* b3    = (const float*)d_in[12];
    float* out = (float*)d_out;

    dim3 grid1(BATCH, SPLIT);
    lidar_reduce_kernel<<<grid1, LIDAR_C>>>(lidar);
    head_kernel<<<BATCH, 1024>>>(wv, wo1, b1, wo2, b2, wo3, b3, out);
}

// round 2
// speedup vs baseline: 1.7926x; 1.7926x over previous
#include <cuda_runtime.h>

// Live computation: out = MLP( (mean_p lidar[b,p,:]) @ wv ).
// All conv / Q / K / attention work is dead: only the zero-padded last query
// row feeds the head, making attention a uniform average over V.

#define BATCH     16
#define N_POINTS  4096
#define LIDAR_C   256
#define D_MODEL   1024
#define H1        128
#define BIN_SIZE  256
#define SPLIT     64                      // point-dim split for reduction
#define PTS_PER_BLK (N_POINTS / SPLIT)    // 64

// scratch partial sums: layout [SPLIT][BATCH][LIDAR_C] = 4 MB
__device__ float g_partial[SPLIT * BATCH * LIDAR_C];

// ---------------------------------------------------------------------------
// Kernel 1: partial column sums of lidar over the point dimension.
// grid (BATCH, SPLIT), 256 threads. float4 loads, 16 in flight per thread.
// Thread layout: c4 = tid&63 (float4 channel), r = tid>>6 (row subgroup 0..3),
// each thread sums 16 rows of its float4 column; smem-fold the 4 subgroups.
// ---------------------------------------------------------------------------
__global__ void __launch_bounds__(256)
lidar_reduce_kernel(const float4* __restrict__ lidar4)
{
    const int b  = blockIdx.x;
    const int s  = blockIdx.y;
    const int c4 = threadIdx.x & 63;
    const int r  = threadIdx.x >> 6;

    const float4* base = lidar4
        + ((size_t)b * N_POINTS + (size_t)s * PTS_PER_BLK + (size_t)r * 16) * 64 + c4;

    float4 acc = make_float4(0.f, 0.f, 0.f, 0.f);
#pragma unroll
    for (int i = 0; i < 16; ++i) {
        float4 v = base[(size_t)i * 64];
        acc.x += v.x; acc.y += v.y; acc.z += v.z; acc.w += v.w;
    }

    __shared__ float4 sp[4][64];
    sp[r][c4] = acc;
    __syncthreads();

    if (r == 0) {
        float4 a = sp[0][c4], bb = sp[1][c4], c = sp[2][c4], d = sp[3][c4];
        float4 t;
        t.x = (a.x + bb.x) + (c.x + d.x);
        t.y = (a.y + bb.y) + (c.y + d.y);
        t.z = (a.z + bb.z) + (c.z + d.z);
        t.w = (a.w + bb.w) + (c.w + d.w);
        ((float4*)g_partial)[((size_t)s * BATCH + b) * 64 + c4] = t;
    }
}

// ---------------------------------------------------------------------------
// Kernel 2: per-batch head, 1024 threads, every stage uses the full block.
//   mean(256) -> bins = mean@wv (1024) -> h1 = lrelu(bins@wo1+b1) (128)
//   -> h2 = lrelu(h1@wo2+b2) (128) -> out = h2@wo3+b3 (256)
// GEMV dots are split across thread-groups + smem tree fold so no thread
// runs a >256-iteration serial loop and no thread sits idle.
// ---------------------------------------------------------------------------
__global__ void __launch_bounds__(1024)
head_kernel(const float* __restrict__ wv,    // [256,1024]
            const float* __restrict__ wo1,   // [1024,128]
            const float* __restrict__ b1,    // [128]
            const float* __restrict__ wo2,   // [128,128]
            const float* __restrict__ b2,    // [128]
            const float* __restrict__ wo3,   // [128,256]
            const float* __restrict__ b3,    // [256]
            float* __restrict__ out)         // [BATCH,256]
{
    const int b   = blockIdx.x;
    const int tid = threadIdx.x;

    __shared__ float s_mean[LIDAR_C];
    __shared__ float s_bins[D_MODEL];
    __shared__ float s_red[1024];
    __shared__ float s_h1[H1];
    __shared__ float s_h2[H1];

    // ---- fold the 64 partials -> mean (coalesced, 4 independent chains) ----
    if (tid < LIDAR_C) {
        const float* p = &g_partial[(size_t)b * LIDAR_C + tid];
        float a0 = 0.f, a1 = 0.f, a2 = 0.f, a3 = 0.f;
#pragma unroll
        for (int s = 0; s < SPLIT; s += 4) {
            a0 += p[(size_t)(s + 0) * (BATCH * LIDAR_C)];
            a1 += p[(size_t)(s + 1) * (BATCH * LIDAR_C)];
            a2 += p[(size_t)(s + 2) * (BATCH * LIDAR_C)];
            a3 += p[(size_t)(s + 3) * (BATCH * LIDAR_C)];
        }
        s_mean[tid] = ((a0 + a1) + (a2 + a3)) * (1.0f / (float)N_POINTS);
    }
    __syncthreads();

    // ---- bins[j] = sum_c mean[c] * wv[c][j], thread-per-j, 4 accumulators --
    {
        float a0 = 0.f, a1 = 0.f, a2 = 0.f, a3 = 0.f;
#pragma unroll 8
        for (int c = 0; c < LIDAR_C; c += 4) {
            a0 += s_mean[c + 0] * __ldg(&wv[(size_t)(c + 0) * D_MODEL + tid]);
            a1 += s_mean[c + 1] * __ldg(&wv[(size_t)(c + 1) * D_MODEL + tid]);
            a2 += s_mean[c + 2] * __ldg(&wv[(size_t)(c + 2) * D_MODEL + tid]);
            a3 += s_mean[c + 3] * __ldg(&wv[(size_t)(c + 3) * D_MODEL + tid]);
        }
        s_bins[tid] = (a0 + a1) + (a2 + a3);
    }
    __syncthreads();

    // ---- h1: 128 outputs x 1024-dot; 8 m-groups of 128, coalesced ---------
    {
        const int j = tid & 127;
        const int g = tid >> 7;
        const float* w  = wo1 + (size_t)(g * 128) * H1 + j;
        const float* bn = s_bins + g * 128;
        float a0 = 0.f, a1 = 0.f;
#pragma unroll 8
        for (int i = 0; i < 128; i += 2) {
            a0 += bn[i]     * __ldg(&w[(size_t)i * H1]);
            a1 += bn[i + 1] * __ldg(&w[(size_t)(i + 1) * H1]);
        }
        s_red[tid] = a0 + a1;
    }
    __syncthreads();
    if (tid < H1) {
        float acc = __ldg(&b1[tid]);
#pragma unroll
        for (int g = 0; g < 8; ++g) acc += s_red[g * 128 + tid];
        s_h1[tid] = (acc > 0.f) ? acc : 0.01f * acc;
    }
    __syncthreads();

    // ---- h2: 128 outputs x 128-dot; 8 m-groups of 16 -----------------------
    {
        const int j = tid & 127;
        const int g = tid >> 7;
        const float* w  = wo2 + (size_t)(g * 16) * H1 + j;
        const float* hh = s_h1 + g * 16;
        float a = 0.f;
#pragma unroll
        for (int i = 0; i < 16; ++i)
            a += hh[i] * __ldg(&w[(size_t)i * H1]);
        s_red[tid] = a;
    }
    __syncthreads();
    if (tid < H1) {
        float acc = __ldg(&b2[tid]);
#pragma unroll
        for (int g = 0; g < 8; ++g) acc += s_red[g * 128 + tid];
        s_h2[tid] = (acc > 0.f) ? acc : 0.01f * acc;
    }
    __syncthreads();

    // ---- out: 256 outputs x 128-dot; 4 m-groups of 32 ----------------------
    {
        const int j = tid & 255;
        const int g = tid >> 8;
        const float* w  = wo3 + (size_t)(g * 32) * BIN_SIZE + j;
        const float* hh = s_h2 + g * 32;
        float a = 0.f;
#pragma unroll
        for (int i = 0; i < 32; ++i)
            a += hh[i] * __ldg(&w[(size_t)i * BIN_SIZE]);
        s_red[tid] = a;
    }
    __syncthreads();
    if (tid < BIN_SIZE) {
        float acc = __ldg(&b3[tid])
                  + (s_red[tid] + s_red[256 + tid])
                  + (s_red[512 + tid] + s_red[768 + tid]);
        out[(size_t)b * BIN_SIZE + tid] = acc;
    }
}

// ---------------------------------------------------------------------------
// Inputs (metadata order):
// 0 feature, 1 lidar, 2 conv1_w, 3 conv2_w, 4 wq, 5 wk, 6 wv,
// 7 wo1, 8 b1, 9 wo2, 10 b2, 11 wo3, 12 b3
// ---------------------------------------------------------------------------
extern "C" void kernel_launch(void* const* d_in, const int* in_sizes, int n_in,
                              void* d_out, int out_size)
{
    const float4* lidar4 = (const float4*)d_in[1];
    const float* wv    = (const float*)d_in[6];
    const float* wo1   = (const float*)d_in[7];
    const float* b1    = (const float*)d_in[8];
    const float* wo2   = (const float*)d_in[9];
    const float* b2    = (const float*)d_in[10];
    const float* wo3   = (const float*)d_in[11];
    const float* b3    = (const float*)d_in[12];
    float* out = (float*)d_out;

    dim3 grid1(BATCH, SPLIT);
    lidar_reduce_kernel<<<grid1, 256>>>(lidar4);
    head_kernel<<<BATCH, 1024>>>(wv, wo1, b1, wo2, b2, wo3, b3, out);
}

// round 3
// speedup vs baseline: 2.2648x; 1.2634x over previous
#include <cuda_runtime.h>

// Live computation: out = MLP( (mean_p lidar[b,p,:]) @ wv ).
// All conv / Q / K / attention work is dead: only the zero-padded last query
// row feeds the head, making attention a uniform average over V.

#define BATCH     16
#define N_POINTS  4096
#define LIDAR_C   256
#define D_MODEL   1024
#define H1        128
#define BIN_SIZE  256
#define SPLIT     64
#define PTS_PER_BLK (N_POINTS / SPLIT)    // 64

// scratch partial sums: layout [SPLIT][BATCH][LIDAR_C] = 4 MB
__device__ float g_partial[SPLIT * BATCH * LIDAR_C];

// ---------------------------------------------------------------------------
// Kernel 1: partial column sums of lidar (DRAM-bound, ~67 MB).
// grid (BATCH, SPLIT), 256 threads, float4 loads, 16 in flight per thread.
// ---------------------------------------------------------------------------
__global__ void __launch_bounds__(256)
lidar_reduce_kernel(const float4* __restrict__ lidar4)
{
    const int b  = blockIdx.x;
    const int s  = blockIdx.y;
    const int c4 = threadIdx.x & 63;
    const int r  = threadIdx.x >> 6;

    const float4* base = lidar4
        + ((size_t)b * N_POINTS + (size_t)s * PTS_PER_BLK + (size_t)r * 16) * 64 + c4;

    float4 acc = make_float4(0.f, 0.f, 0.f, 0.f);
#pragma unroll
    for (int i = 0; i < 16; ++i) {
        float4 v = base[(size_t)i * 64];
        acc.x += v.x; acc.y += v.y; acc.z += v.z; acc.w += v.w;
    }

    __shared__ float4 sp[4][64];
    sp[r][c4] = acc;
    __syncthreads();

    if (r == 0) {
        float4 a = sp[0][c4], bb = sp[1][c4], c = sp[2][c4], d = sp[3][c4];
        float4 t;
        t.x = (a.x + bb.x) + (c.x + d.x);
        t.y = (a.y + bb.y) + (c.y + d.y);
        t.z = (a.z + bb.z) + (c.z + d.z);
        t.w = (a.w + bb.w) + (c.w + d.w);
        ((float4*)g_partial)[((size_t)s * BATCH + b) * 64 + c4] = t;
    }
}

// ---------------------------------------------------------------------------
// Kernel 2: per-batch head, 1024 threads. All weight loads are LDG.128
// (thread owns 4 adjacent outputs), all stages use the full block via
// k-group splits + smem folds. ~3.5K warp-LDGs total (was ~14K scalar).
// ---------------------------------------------------------------------------
__global__ void __launch_bounds__(1024)
head_kernel(const float4* __restrict__ wv4,    // [256][256] f4
            const float4* __restrict__ wo14,   // [1024][32] f4
            const float4* __restrict__ b14,    // [32] f4
            const float4* __restrict__ wo24,   // [128][32] f4
            const float4* __restrict__ b24,    // [32] f4
            const float4* __restrict__ wo34,   // [128][64] f4
            const float4* __restrict__ b34,    // [64] f4
            float4* __restrict__ out4)         // [BATCH][64] f4
{
    const int b   = blockIdx.x;
    const int tid = threadIdx.x;

    __shared__ float  s_mean[LIDAR_C];
    __shared__ float  s_bins[D_MODEL];
    __shared__ float  s_h1[H1];
    __shared__ float  s_h2[H1];
    __shared__ float4 s_red[1024];             // 16 KB, reused per stage

    // ---- fold 64 partials -> mean. 4 s-groups x 64 f4 channels ------------
    {
        const int c4 = tid & 63;
        const int sg = tid >> 6;               // 0..15, use first 4 groups
        if (sg < 4) {
            const float4* p = ((const float4*)g_partial) + (size_t)b * 64 + c4;
            float4 acc = make_float4(0.f, 0.f, 0.f, 0.f);
#pragma unroll
            for (int i = 0; i < 16; ++i) {
                float4 v = p[(size_t)(sg * 16 + i) * (BATCH * 64)];
                acc.x += v.x; acc.y += v.y; acc.z += v.z; acc.w += v.w;
            }
            s_red[sg * 64 + c4] = acc;
        }
    }
    __syncthreads();
    if (tid < 64) {
        float4 a = s_red[tid], bb = s_red[64 + tid],
               c = s_red[128 + tid], d = s_red[192 + tid];
        const float inv = 1.0f / (float)N_POINTS;
        s_mean[tid * 4 + 0] = ((a.x + bb.x) + (c.x + d.x)) * inv;
        s_mean[tid * 4 + 1] = ((a.y + bb.y) + (c.y + d.y)) * inv;
        s_mean[tid * 4 + 2] = ((a.z + bb.z) + (c.z + d.z)) * inv;
        s_mean[tid * 4 + 3] = ((a.w + bb.w) + (c.w + d.w)) * inv;
    }
    __syncthreads();

    // ---- bins = mean @ wv : 256 j4-groups x 4 k-groups of 64 --------------
    {
        const int j4 = tid & 255;
        const int kg = tid >> 8;               // 0..3
        const float4* w = wv4 + (size_t)(kg * 64) * 256 + j4;
        const float*  m = s_mean + kg * 64;
        float4 acc = make_float4(0.f, 0.f, 0.f, 0.f);
#pragma unroll 8
        for (int k = 0; k < 64; ++k) {
            float4 v = __ldg(&w[(size_t)k * 256]);
            float  s = m[k];
            acc.x += s * v.x; acc.y += s * v.y; acc.z += s * v.z; acc.w += s * v.w;
        }
        s_red[kg * 256 + j4] = acc;
    }
    __syncthreads();
    if (tid < 256) {
        float4 a = s_red[tid], bb = s_red[256 + tid],
               c = s_red[512 + tid], d = s_red[768 + tid];
        s_bins[tid * 4 + 0] = (a.x + bb.x) + (c.x + d.x);
        s_bins[tid * 4 + 1] = (a.y + bb.y) + (c.y + d.y);
        s_bins[tid * 4 + 2] = (a.z + bb.z) + (c.z + d.z);
        s_bins[tid * 4 + 3] = (a.w + bb.w) + (c.w + d.w);
    }
    __syncthreads();

    // ---- h1 = lrelu(bins @ wo1 + b1): 32 j4 x 32 k-groups of 32 -----------
    {
        const int j4 = tid & 31;
        const int kg = tid >> 5;               // 0..31
        const float4* w = wo14 + (size_t)(kg * 32) * 32 + j4;
        const float*  m = s_bins + kg * 32;
        float4 acc = make_float4(0.f, 0.f, 0.f, 0.f);
#pragma unroll 8
        for (int k = 0; k < 32; ++k) {
            float4 v = __ldg(&w[(size_t)k * 32]);
            float  s = m[k];
            acc.x += s * v.x; acc.y += s * v.y; acc.z += s * v.z; acc.w += s * v.w;
        }
        s_red[kg * 32 + j4] = acc;
    }
    __syncthreads();
    if (tid < 32) {
        float4 acc = __ldg(&b14[tid]);
#pragma unroll
        for (int g = 0; g < 32; ++g) {
            float4 v = s_red[g * 32 + tid];
            acc.x += v.x; acc.y += v.y; acc.z += v.z; acc.w += v.w;
        }
        s_h1[tid * 4 + 0] = (acc.x > 0.f) ? acc.x : 0.01f * acc.x;
        s_h1[tid * 4 + 1] = (acc.y > 0.f) ? acc.y : 0.01f * acc.y;
        s_h1[tid * 4 + 2] = (acc.z > 0.f) ? acc.z : 0.01f * acc.z;
        s_h1[tid * 4 + 3] = (acc.w > 0.f) ? acc.w : 0.01f * acc.w;
    }
    __syncthreads();

    // ---- h2 = lrelu(h1 @ wo2 + b2): 32 j4 x 32 k-groups of 4 --------------
    {
        const int j4 = tid & 31;
        const int kg = tid >> 5;
        const float4* w = wo24 + (size_t)(kg * 4) * 32 + j4;
        const float*  m = s_h1 + kg * 4;
        float4 acc = make_float4(0.f, 0.f, 0.f, 0.f);
#pragma unroll
        for (int k = 0; k < 4; ++k) {
            float4 v = __ldg(&w[(size_t)k * 32]);
            float  s = m[k];
            acc.x += s * v.x; acc.y += s * v.y; acc.z += s * v.z; acc.w += s * v.w;
        }
        s_red[kg * 32 + j4] = acc;
    }
    __syncthreads();
    if (tid < 32) {
        float4 acc = __ldg(&b24[tid]);
#pragma unroll
        for (int g = 0; g < 32; ++g) {
            float4 v = s_red[g * 32 + tid];
            acc.x += v.x; acc.y += v.y; acc.z += v.z; acc.w += v.w;
        }
        s_h2[tid * 4 + 0] = (acc.x > 0.f) ? acc.x : 0.01f * acc.x;
        s_h2[tid * 4 + 1] = (acc.y > 0.f) ? acc.y : 0.01f * acc.y;
        s_h2[tid * 4 + 2] = (acc.z > 0.f) ? acc.z : 0.01f * acc.z;
        s_h2[tid * 4 + 3] = (acc.w > 0.f) ? acc.w : 0.01f * acc.w;
    }
    __syncthreads();

    // ---- out = h2 @ wo3 + b3: 64 j4 x 16 k-groups of 8 --------------------
    {
        const int j4 = tid & 63;
        const int kg = tid >> 6;               // 0..15
        const float4* w = wo34 + (size_t)(kg * 8) * 64 + j4;
        const float*  m = s_h2 + kg * 8;
        float4 acc = make_float4(0.f, 0.f, 0.f, 0.f);
#pragma unroll
        for (int k = 0; k < 8; ++k) {
            float4 v = __ldg(&w[(size_t)k * 64]);
            float  s = m[k];
            acc.x += s * v.x; acc.y += s * v.y; acc.z += s * v.z; acc.w += s * v.w;
        }
        s_red[kg * 64 + j4] = acc;
    }
    __syncthreads();
    if (tid < 64) {
        float4 acc = __ldg(&b34[tid]);
#pragma unroll
        for (int g = 0; g < 16; ++g) {
            float4 v = s_red[g * 64 + tid];
            acc.x += v.x; acc.y += v.y; acc.z += v.z; acc.w += v.w;
        }
        out4[(size_t)b * 64 + tid] = acc;
    }
}

// ---------------------------------------------------------------------------
// Inputs: 0 feature, 1 lidar, 2 conv1_w, 3 conv2_w, 4 wq, 5 wk, 6 wv,
//         7 wo1, 8 b1, 9 wo2, 10 b2, 11 wo3, 12 b3
// ---------------------------------------------------------------------------
extern "C" void kernel_launch(void* const* d_in, const int* in_sizes, int n_in,
                              void* d_out, int out_size)
{
    const float4* lidar4 = (const float4*)d_in[1];
    const float4* wv4    = (const float4*)d_in[6];
    const float4* wo14   = (const float4*)d_in[7];
    const float4* b14    = (const float4*)d_in[8];
    const float4* wo24   = (const float4*)d_in[9];
    const float4* b24    = (const float4*)d_in[10];
    const float4* wo34   = (const float4*)d_in[11];
    const float4* b34    = (const float4*)d_in[12];
    float4* out4 = (float4*)d_out;

    dim3 grid1(BATCH, SPLIT);
    lidar_reduce_kernel<<<grid1, 256>>>(lidar4);
    head_kernel<<<BATCH, 1024>>>(wv4, wo14, b14, wo24, b24, wo34, b34, out4);
}